// round 8
// baseline (speedup 1.0000x reference)
#include <cuda_runtime.h>
#include <cuda_fp16.h>
#include <cstdint>

// MorphLayer == conv2d(x, exp(k1)-exp(k2), VALID 3x3) + bias  (exact reduction)
// B=32 C=64 H=W=64 -> Ho=Wo=62, F=128.
// HMMA implicit-GEMM, single fp16 product, fp32 acc.
// 296 CTAs (2 f-halves x 148), 2 CTAs/SM, weights resident (72KB), rolling
// 4-row slab. ROUND 8: 128-thread CTAs, warp tile M=64 (2oh x 32w) x N=32
// -> LDSM smem traffic 192B/MMA (was 256) so the tensor pipe binds.

#define Hn  64
#define Wn  64
#define HOn 62
#define WOn 62
#define Fn  128
#define Cn  64

#define SLAB_ROWS  258                     // 4 ring slots * 64 + 2 pad rows
#define SLAB_BYTES (SLAB_ROWS * 128)       // 33024
#define WOFF       SLAB_BYTES
#define WRES_BYTES (9 * 64 * 128)          // 73728
#define SMEM_TOTAL (WOFF + WRES_BYTES)     // 106752 -> 2 CTAs/SM

#define JOBS_PER_HALF 992                  // 31 h-tiles * 32 batch
#define NCTA_PER_HALF 148
#define JOBS_PER_CTA  7                    // ceil(992/148)

// Single fp16 weights, SW128-swizzled: [tap][f=128][c=64]
__device__ __align__(16) unsigned char g_W[9 * 16384];

__device__ __forceinline__ uint32_t smem_u32(const void* p) {
    uint32_t a;
    asm("{ .reg .u64 t; cvta.to.shared.u64 t, %1; cvt.u32.u64 %0, t; }" : "=r"(a) : "l"(p));
    return a;
}

#define LDSM4(r, addr)                                                          \
    asm volatile("ldmatrix.sync.aligned.m8n8.x4.shared.b16 {%0,%1,%2,%3}, [%4];" \
                 : "=r"((r)[0]), "=r"((r)[1]), "=r"((r)[2]), "=r"((r)[3])        \
                 : "r"(addr))

#define MMA(d, a, b0, b1)                                                       \
    asm volatile("mma.sync.aligned.m16n8k16.row.col.f32.f16.f16.f32 "           \
                 "{%0,%1,%2,%3}, {%4,%5,%6,%7}, {%8,%9}, {%0,%1,%2,%3};"        \
                 : "+f"((d)[0]), "+f"((d)[1]), "+f"((d)[2]), "+f"((d)[3])        \
                 : "r"((a)[0]), "r"((a)[1]), "r"((a)[2]), "r"((a)[3]),           \
                   "r"(b0), "r"(b1))

// ---------------- weight prep: w = exp(k1)-exp(k2) -> fp16, swizzled ----------------
__global__ void prep_w(const float* __restrict__ k1, const float* __restrict__ k2) {
    int idx = blockIdx.x * 256 + threadIdx.x;       // 73728 = 9*128*64
    int t   = idx >> 13;
    int rem = idx & 8191;
    int f   = rem >> 6;
    int c   = rem & 63;
    int src = (t * 64 + c) * 128 + f;               // k1 layout (kh,kw,C,F)
    float w = expf(k1[src]) - expf(k2[src]);
    __half h = __float2half_rn(w);
    unsigned off = (unsigned)(f * 128 + c * 2);
    off = off ^ ((off >> 3) & 0x70);                // SW128 swizzle
    *(unsigned short*)(g_W + t * 16384 + off) = *(unsigned short*)&h;
}

// ---------------- main kernel ----------------
extern __shared__ char smem_raw[];

__device__ __forceinline__ void build_rows(const float* __restrict__ xb,
                                           char* smem, int tid,
                                           int gh0, int nrows) {
    // tasks = nrows*512 ; 128 threads -> 4*nrows iters
    #pragma unroll 1
    for (int it = 0; it < 4 * nrows; it++) {
        int t    = tid + it * 128;
        int gw   = t & 63;
        int cg   = (t >> 6) & 7;
        int hloc = t >> 9;
        int gh   = gh0 + hloc;
        const float* xp = xb + (size_t)(cg * 8) * (Hn * Wn) + gh * Wn + gw;
        unsigned short hs[8];
        #pragma unroll
        for (int i = 0; i < 8; i++) {
            __half h = __float2half_rn(xp[(size_t)i * (Hn * Wn)]);
            hs[i] = *(unsigned short*)&h;
        }
        unsigned row  = (unsigned)((gh & 3) * 64 + gw);     // ring slot
        unsigned boff = row * 128 + cg * 16;
        unsigned sw   = boff ^ ((boff >> 3) & 0x70);
        *(uint4*)(smem + sw) =
            make_uint4((uint32_t)hs[0] | ((uint32_t)hs[1] << 16),
                       (uint32_t)hs[2] | ((uint32_t)hs[3] << 16),
                       (uint32_t)hs[4] | ((uint32_t)hs[5] << 16),
                       (uint32_t)hs[6] | ((uint32_t)hs[7] << 16));
    }
}

__global__ void __launch_bounds__(128, 2)
conv_hmma_kernel(const float* __restrict__ x,
                 const float* __restrict__ bias,
                 float* __restrict__ out) {
    const int tid  = threadIdx.x;
    const int lane = tid & 31;
    const int wid  = tid >> 5;         // 0..3
    const int wn   = wid & 1;          // f 32-half within CTA's 64 filters
    const int wmw  = wid >> 1;         // w 32-half
    const int fh   = blockIdx.x;       // filter half of 128
    const int cid  = blockIdx.y;       // worker id

    const int jstart = cid * JOBS_PER_CTA;
    if (jstart >= JOBS_PER_HALF) return;
    const int jend = (jstart + JOBS_PER_CTA < JOBS_PER_HALF)
                   ? jstart + JOBS_PER_CTA : JOBS_PER_HALF;

    const uint32_t sb = smem_u32(smem_raw);

    // ---- resident weight load: 64 filters x 9 taps (72KB), once per CTA ----
    {
        const unsigned char* src = g_W + fh * 8192;
        #pragma unroll
        for (int j = 0; j < 36; j++) {
            int k = tid + j * 128;                  // 4608 chunks of 16B
            int tap = k >> 9;
            int rem = k & 511;
            uint32_t dst = sb + WOFF + (uint32_t)k * 16;
            asm volatile("cp.async.cg.shared.global [%0], [%1], 16;"
                         :: "r"(dst), "l"(src + (size_t)tap * 16384 + rem * 16));
        }
        asm volatile("cp.async.commit_group;");
    }

    // zero pad rows 256..257 (overflow target; feeds only discarded outputs)
    if (tid < 16) {
        *(uint4*)(smem_raw + 256 * 128 + tid * 16) = make_uint4(0u, 0u, 0u, 0u);
    }

    // lane-constant addressing
    const uint32_t a_hi16  = (uint32_t)(lane >> 4) * 16;
    const int      fb0     = wn * 32 + (lane & 7) + ((lane >> 4) & 1) * 8;
    const uint32_t b_off16 = (uint32_t)((lane >> 3) & 1) * 16;
    const uint32_t swzB    = (uint32_t)(fb0 & 7) << 4;
    const uint32_t wBase   = sb + WOFF + (uint32_t)fb0 * 128;
    const int      mrow0   = wmw * 32 + (lane & 15);   // w coordinate base

    // bias hoisted (constant across tiles)
    float bv0[4], bv1[4];
    #pragma unroll
    for (int ni = 0; ni < 4; ni++) {
        const int f = fh * 64 + wn * 32 + ni * 8 + (lane & 3) * 2;
        bv0[ni] = __ldg(bias + f);
        bv1[ni] = __ldg(bias + f + 1);
    }

    // ---- build slab for first job ----
    int j0bz = jstart / 31;
    int j0ht = jstart - j0bz * 31;
    build_rows(x + (size_t)j0bz * Cn * Hn * Wn, smem_raw, tid, 2 * j0ht, 4);
    asm volatile("cp.async.wait_group 0;");

    #pragma unroll 1
    for (int j = jstart; j < jend; j++) {
        const int bz = j / 31;
        const int ht = j - bz * 31;
        const int h0 = 2 * ht;

        __syncthreads();               // slab writes visible

        float acc[2][2][4][4];         // [oh][wblk][ni][quad] = 64 regs
        #pragma unroll
        for (int o = 0; o < 2; o++)
            #pragma unroll
            for (int wb = 0; wb < 2; wb++)
                #pragma unroll
                for (int ni = 0; ni < 4; ni++)
                    #pragma unroll
                    for (int q = 0; q < 4; q++) acc[o][wb][ni][q] = 0.0f;

        #pragma unroll 1
        for (int t = 0; t < 9; t++) {
            const int ki = t / 3;
            const int kj = t - 3 * ki;
            const int slot0 = (h0 + ki) & 3;       // oh = h0
            const int slot1 = (slot0 + 1) & 3;     // oh = h0+1
            const int sb0   = slot0 * 64 + mrow0 + kj;
            const int sb1   = slot1 * 64 + mrow0 + kj;
            const uint32_t swzA   = (uint32_t)(sb0 & 7) << 4;   // same for both
            const uint32_t aBase0 = sb + (uint32_t)sb0 * 128;
            const uint32_t aBase1 = sb + (uint32_t)sb1 * 128;
            const uint32_t bTap   = wBase + (uint32_t)t * 8192;

            #pragma unroll
            for (int kc = 0; kc < 4; kc++) {
                const uint32_t aoff = ((uint32_t)(kc * 32) + a_hi16) ^ swzA;
                const uint32_t boff = ((uint32_t)(kc * 32) + b_off16) ^ swzB;

                uint32_t A[2][2][4], Bf[2][4];
                LDSM4(A[0][0], aBase0 + aoff);
                LDSM4(A[0][1], aBase0 + 2048 + aoff);   // +16 w rows
                LDSM4(A[1][0], aBase1 + aoff);
                LDSM4(A[1][1], aBase1 + 2048 + aoff);
                LDSM4(Bf[0], bTap + boff);
                LDSM4(Bf[1], bTap + 2048 + boff);

                #pragma unroll
                for (int o = 0; o < 2; o++)
                    #pragma unroll
                    for (int wb = 0; wb < 2; wb++)
                        #pragma unroll
                        for (int bi = 0; bi < 2; bi++) {
                            MMA(acc[o][wb][2 * bi],     A[o][wb], Bf[bi][0], Bf[bi][1]);
                            MMA(acc[o][wb][2 * bi + 1], A[o][wb], Bf[bi][2], Bf[bi][3]);
                        }
            }
        }

        __syncthreads();               // all reads done; slab reusable

        // ---- build slab rows for next job (overlaps epilogue) ----
        if (j + 1 < jend) {
            const int nbz = (j + 1) / 31;
            const int nht = (j + 1) - nbz * 31;
            const float* nxb = x + (size_t)nbz * Cn * Hn * Wn;
            if (nht != 0) {
                build_rows(nxb, smem_raw, tid, 2 * nht + 2, 2);   // 2 new rows
            } else {
                build_rows(nxb, smem_raw, tid, 0, 4);             // batch switch
            }
        }

        // ---- epilogue: acc -> out[bz, f, oh, ow] + bias ----
        #pragma unroll
        for (int ni = 0; ni < 4; ni++) {
            const int f = fh * 64 + wn * 32 + ni * 8 + (lane & 3) * 2;
            #pragma unroll
            for (int o = 0; o < 2; o++) {
                const int oh = h0 + o;
                float* p0 = out + (((size_t)bz * Fn + f) * HOn + oh) * WOn;
                float* p1 = p0 + (size_t)HOn * WOn;
                #pragma unroll
                for (int wb = 0; wb < 2; wb++) {
                    const int w0 = wmw * 32 + wb * 16 + (lane >> 2);  // < 62 always
                    const int w1 = w0 + 8;
                    p0[w0] = acc[o][wb][ni][0] + bv0[ni];
                    p1[w0] = acc[o][wb][ni][1] + bv1[ni];
                    if (w1 < WOn) {
                        p0[w1] = acc[o][wb][ni][2] + bv0[ni];
                        p1[w1] = acc[o][wb][ni][3] + bv1[ni];
                    }
                }
            }
        }
    }
}

extern "C" void kernel_launch(void* const* d_in, const int* in_sizes, int n_in,
                              void* d_out, int out_size) {
    const float* x    = (const float*)d_in[0];   // (32,64,64,64)
    const float* k1   = (const float*)d_in[1];   // (3,3,64,128)
    const float* k2   = (const float*)d_in[2];   // (3,3,64,128)
    const float* bias = (const float*)d_in[3];   // (128,)
    float* out = (float*)d_out;                  // (32,128,62,62)
    (void)in_sizes; (void)n_in; (void)out_size;

    cudaFuncSetAttribute(conv_hmma_kernel,
                         cudaFuncAttributeMaxDynamicSharedMemorySize, SMEM_TOTAL);

    prep_w<<<288, 256>>>(k1, k2);
    dim3 grid(2, NCTA_PER_HALF);       // 296 CTAs = one full wave at 2/SM
    conv_hmma_kernel<<<grid, 128, SMEM_TOTAL>>>(x, bias, out);
}

// round 9
// speedup vs baseline: 1.0282x; 1.0282x over previous
#include <cuda_runtime.h>
#include <cuda_fp16.h>
#include <cstdint>

// MorphLayer == conv2d(x, exp(k1)-exp(k2), VALID 3x3) + bias  (exact reduction)
// B=32 C=64 H=W=64 -> Ho=Wo=62, F=128.
// HMMA implicit-GEMM, single fp16 product, fp32 acc.
// ROUND 9: one 512-thread CTA per SM (148 total). CTA job: M=256 (4oh x 64w)
// x N=128 (ALL filters resident: 144KB). 16 warps = 4m x 4n, warp tile 64x32
// (MMA:LDSM = 16:6). Rolling 6-slot slab ring (slot = gh % 6), 49.4KB.
// Jobs: 16 h-tiles x 32 batch = 512, blocked consecutively over 148 CTAs.

#define Hn  64
#define Wn  64
#define HOn 62
#define WOn 62
#define Fn  128
#define Cn  64

#define SLAB_ROWS  386                     // 6 slots * 64 + 2 overflow pad rows
#define SLAB_BYTES (SLAB_ROWS * 128)       // 49408
#define WOFF       SLAB_BYTES
#define WRES_BYTES (9 * 128 * 128)         // 147456 (all taps, all filters)
#define SMEM_TOTAL (WOFF + WRES_BYTES)     // 196864 -> 1 CTA/SM

#define NCTA  148
#define NJOBS 512                          // 16 h-tiles * 32 batch

// fp16 weights, SW128-swizzled: [tap][f=128][c=64]
__device__ __align__(16) unsigned char g_W[9 * 16384];

__device__ __forceinline__ uint32_t smem_u32(const void* p) {
    uint32_t a;
    asm("{ .reg .u64 t; cvta.to.shared.u64 t, %1; cvt.u32.u64 %0, t; }" : "=r"(a) : "l"(p));
    return a;
}

#define LDSM4(r, addr)                                                          \
    asm volatile("ldmatrix.sync.aligned.m8n8.x4.shared.b16 {%0,%1,%2,%3}, [%4];" \
                 : "=r"((r)[0]), "=r"((r)[1]), "=r"((r)[2]), "=r"((r)[3])        \
                 : "r"(addr))

#define MMA(d, a, b0, b1)                                                       \
    asm volatile("mma.sync.aligned.m16n8k16.row.col.f32.f16.f16.f32 "           \
                 "{%0,%1,%2,%3}, {%4,%5,%6,%7}, {%8,%9}, {%0,%1,%2,%3};"        \
                 : "+f"((d)[0]), "+f"((d)[1]), "+f"((d)[2]), "+f"((d)[3])        \
                 : "r"((a)[0]), "r"((a)[1]), "r"((a)[2]), "r"((a)[3]),           \
                   "r"(b0), "r"(b1))

// ---------------- weight prep: w = exp(k1)-exp(k2) -> fp16, swizzled ----------------
__global__ void prep_w(const float* __restrict__ k1, const float* __restrict__ k2) {
    int idx = blockIdx.x * 256 + threadIdx.x;       // 73728 = 9*128*64
    int t   = idx >> 13;
    int rem = idx & 8191;
    int f   = rem >> 6;
    int c   = rem & 63;
    int src = (t * 64 + c) * 128 + f;               // k1 layout (kh,kw,C,F)
    float w = expf(k1[src]) - expf(k2[src]);
    __half h = __float2half_rn(w);
    unsigned off = (unsigned)(f * 128 + c * 2);
    off = off ^ ((off >> 3) & 0x70);                // SW128 swizzle
    *(unsigned short*)(g_W + t * 16384 + off) = *(unsigned short*)&h;
}

// ---------------- main kernel ----------------
extern __shared__ char smem_raw[];

__device__ __forceinline__ void build_rows(const float* __restrict__ xb,
                                           char* smem, int tid,
                                           int gh0, int nrows) {
    // nrows*512 tasks, 512 threads -> nrows iters; slot = gh % 6
    #pragma unroll 1
    for (int it = 0; it < nrows; it++) {
        int t    = tid + it * 512;
        int gw   = t & 63;
        int cg   = (t >> 6) & 7;
        int gh   = gh0 + (t >> 9);
        unsigned short hs[8];
        if (gh < Hn) {
            const float* xp = xb + (size_t)(cg * 8) * (Hn * Wn) + gh * Wn + gw;
            #pragma unroll
            for (int i = 0; i < 8; i++) {
                __half h = __float2half_rn(xp[(size_t)i * (Hn * Wn)]);
                hs[i] = *(unsigned short*)&h;
            }
        } else {
            #pragma unroll
            for (int i = 0; i < 8; i++) hs[i] = 0;
        }
        int slot = gh % 6;
        unsigned row  = (unsigned)(slot * 64 + gw);
        unsigned boff = row * 128 + cg * 16;
        unsigned sw   = boff ^ ((boff >> 3) & 0x70);
        *(uint4*)(smem + sw) =
            make_uint4((uint32_t)hs[0] | ((uint32_t)hs[1] << 16),
                       (uint32_t)hs[2] | ((uint32_t)hs[3] << 16),
                       (uint32_t)hs[4] | ((uint32_t)hs[5] << 16),
                       (uint32_t)hs[6] | ((uint32_t)hs[7] << 16));
    }
}

__global__ void __launch_bounds__(512, 1)
conv_hmma_kernel(const float* __restrict__ x,
                 const float* __restrict__ bias,
                 float* __restrict__ out) {
    const int tid  = threadIdx.x;
    const int lane = tid & 31;
    const int wid  = tid >> 5;         // 0..15
    const int wm   = wid & 3;          // m-block: oh-pair = wm>>1, w-half = wm&1
    const int wn   = wid >> 2;         // n-block: 32 filters
    const int cid  = blockIdx.x;

    int jstart, jcount;
    if (cid < 68) { jstart = cid * 4;              jcount = 4; }
    else          { jstart = 272 + (cid - 68) * 3; jcount = 3; }

    const uint32_t sb = smem_u32(smem_raw);

    // ---- resident weight load: ALL 128 filters x 9 taps (144KB) ----
    {
        #pragma unroll
        for (int j = 0; j < 18; j++) {
            int k = tid + j * 512;                  // 9216 chunks of 16B
            uint32_t dst = sb + WOFF + (uint32_t)k * 16;
            asm volatile("cp.async.cg.shared.global [%0], [%1], 16;"
                         :: "r"(dst), "l"(g_W + (size_t)k * 16));
        }
        asm volatile("cp.async.commit_group;");
    }

    // zero overflow pad rows 384..385 (feeds only discarded ow>=62 outputs)
    if (tid < 16) {
        *(uint4*)(smem_raw + 384 * 128 + tid * 16) = make_uint4(0u, 0u, 0u, 0u);
    }

    // lane-constant addressing
    const uint32_t a_hi16  = (uint32_t)(lane >> 4) * 16;
    const int      fb0     = wn * 32 + (lane & 7) + ((lane >> 4) & 1) * 8;
    const uint32_t b_off16 = (uint32_t)((lane >> 3) & 1) * 16;
    const uint32_t swzB    = (uint32_t)(fb0 & 7) << 4;
    const uint32_t wBase   = sb + WOFF + (uint32_t)fb0 * 128;
    const int      arow0   = (wm & 1) * 32 + (lane & 15);   // in-slot w base
    const int      ohl0    = 2 * (wm >> 1);                 // warp's first oh offset

    // ---- build slab for first job (6 rows) ----
    {
        int bz0 = jstart >> 4;
        int ht0 = jstart & 15;
        build_rows(x + (size_t)bz0 * Cn * Hn * Wn, smem_raw, tid, 4 * ht0, 6);
    }
    asm volatile("cp.async.wait_group 0;");

    #pragma unroll 1
    for (int jj = 0; jj < jcount; jj++) {
        const int j  = jstart + jj;
        const int bz = j >> 4;
        const int ht = j & 15;
        const int h0 = 4 * ht;

        __syncthreads();               // slab + weights visible

        float acc[2][2][4][4];         // [o][wb][ni][quad] = 64 regs
        #pragma unroll
        for (int o = 0; o < 2; o++)
            #pragma unroll
            for (int wb = 0; wb < 2; wb++)
                #pragma unroll
                for (int ni = 0; ni < 4; ni++)
                    #pragma unroll
                    for (int q = 0; q < 4; q++) acc[o][wb][ni][q] = 0.0f;

        #pragma unroll 1
        for (int t = 0; t < 9; t++) {
            const int ki = t / 3;
            const int kj = t - 3 * ki;
            const int gh0r = h0 + ohl0 + ki;
            const int sb0  = (gh0r % 6) * 64 + arow0 + kj;
            const int sb1  = ((gh0r + 1) % 6) * 64 + arow0 + kj;
            const uint32_t swzA0  = (uint32_t)(sb0 & 7) << 4;
            const uint32_t swzA1  = (uint32_t)(sb1 & 7) << 4;
            const uint32_t aBase0 = sb + (uint32_t)sb0 * 128;
            const uint32_t aBase1 = sb + (uint32_t)sb1 * 128;
            const uint32_t bTap   = wBase + (uint32_t)t * 16384;

            #pragma unroll
            for (int kc = 0; kc < 4; kc++) {
                const uint32_t ak   = (uint32_t)(kc * 32) + a_hi16;
                const uint32_t boff = ((uint32_t)(kc * 32) + b_off16) ^ swzB;

                uint32_t A[2][2][4], Bf[2][4];
                LDSM4(A[0][0], aBase0 + (ak ^ swzA0));
                LDSM4(A[0][1], aBase0 + 2048 + (ak ^ swzA0));   // +16 w rows
                LDSM4(A[1][0], aBase1 + (ak ^ swzA1));
                LDSM4(A[1][1], aBase1 + 2048 + (ak ^ swzA1));
                LDSM4(Bf[0], bTap + boff);
                LDSM4(Bf[1], bTap + 2048 + boff);

                #pragma unroll
                for (int o = 0; o < 2; o++)
                    #pragma unroll
                    for (int wb = 0; wb < 2; wb++)
                        #pragma unroll
                        for (int bi = 0; bi < 2; bi++) {
                            MMA(acc[o][wb][2 * bi],     A[o][wb], Bf[bi][0], Bf[bi][1]);
                            MMA(acc[o][wb][2 * bi + 1], A[o][wb], Bf[bi][2], Bf[bi][3]);
                        }
            }
        }

        __syncthreads();               // all reads done; ring slots reusable

        // ---- build slab rows for next job (overlaps epilogue) ----
        if (jj + 1 < jcount) {
            const int nj  = j + 1;
            const int nbz = nj >> 4;
            const int nht = nj & 15;
            const float* nxb = x + (size_t)nbz * Cn * Hn * Wn;
            if (nht != 0) build_rows(nxb, smem_raw, tid, 4 * nht + 2, 4);
            else          build_rows(nxb, smem_raw, tid, 0, 6);
        }

        // ---- epilogue: acc -> out[bz, f, oh, ow] + bias ----
        #pragma unroll
        for (int o = 0; o < 2; o++) {
            const int oh = h0 + ohl0 + o;
            if (oh >= HOn) continue;
            #pragma unroll
            for (int ni = 0; ni < 4; ni++) {
                const int f = wn * 32 + ni * 8 + (lane & 3) * 2;
                const float b0 = __ldg(bias + f);
                const float b1 = __ldg(bias + f + 1);
                float* p0 = out + (((size_t)bz * Fn + f) * HOn + oh) * WOn;
                float* p1 = p0 + (size_t)HOn * WOn;
                #pragma unroll
                for (int wb = 0; wb < 2; wb++) {
                    const int w0 = (wm & 1) * 32 + wb * 16 + (lane >> 2);
                    const int w1 = w0 + 8;
                    p0[w0] = acc[o][wb][ni][0] + b0;
                    p1[w0] = acc[o][wb][ni][1] + b1;
                    if (w1 < WOn) {
                        p0[w1] = acc[o][wb][ni][2] + b0;
                        p1[w1] = acc[o][wb][ni][3] + b1;
                    }
                }
            }
        }
    }
}

extern "C" void kernel_launch(void* const* d_in, const int* in_sizes, int n_in,
                              void* d_out, int out_size) {
    const float* x    = (const float*)d_in[0];   // (32,64,64,64)
    const float* k1   = (const float*)d_in[1];   // (3,3,64,128)
    const float* k2   = (const float*)d_in[2];   // (3,3,64,128)
    const float* bias = (const float*)d_in[3];   // (128,)
    float* out = (float*)d_out;                  // (32,128,62,62)
    (void)in_sizes; (void)n_in; (void)out_size;

    cudaFuncSetAttribute(conv_hmma_kernel,
                         cudaFuncAttributeMaxDynamicSharedMemorySize, SMEM_TOTAL);

    prep_w<<<288, 256>>>(k1, k2);
    conv_hmma_kernel<<<NCTA, 512, SMEM_TOTAL>>>(x, bias, out);
}